// round 3
// baseline (speedup 1.0000x reference)
#include <cuda_runtime.h>
#include <math.h>

#define HH 128
#define WW 224
#define NN 4
#define HW (HH*WW)   // 28672

typedef unsigned long long u64;

// ---------------- f32x2 packed helpers (sm_100 FFMA2 path) -----------------
__device__ __forceinline__ u64 pk2(float lo, float hi) {
    u64 r; asm("mov.b64 %0, {%1, %2};" : "=l"(r) : "f"(lo), "f"(hi)); return r;
}
__device__ __forceinline__ void upk2(u64 v, float& lo, float& hi) {
    asm("mov.b64 {%0, %1}, %2;" : "=f"(lo), "=f"(hi) : "l"(v));
}
__device__ __forceinline__ void fma2(u64& d, u64 a, u64 b) {
    asm("fma.rn.f32x2 %0, %1, %2, %0;" : "+l"(d) : "l"(a), "l"(b));
}

// ---------------- scratch (static __device__ globals) -----------------------
__device__ float g_Ar[(size_t)NN*144*HW];
__device__ float g_Ai[(size_t)NN*144*HW];
__device__ float g_Br[(size_t)NN*144*HW];
__device__ float g_Bi[(size_t)NN*144*HW];
__device__ float g_mr[144], g_sr[144], g_mi[144], g_si[144];
__device__ float2 g_partR[144*16];
__device__ float2 g_partI[144*16];

// ---------------- fused complex 3x3 conv, f32x2 packed ---------------------
// Output tile: 16(h) x 32(w); 256 threads; each thread owns a 2-pixel pair
// packed into one f32x2 lanepair, for COUT_T output channels.
// accR is split (Rp - Rm) so no negated weights are needed.
template<int COUT_T, bool CPLX>
__global__ __launch_bounds__(256, 2)
void conv3x3(const float* __restrict__ xr, const float* __restrict__ xi,
             const float* __restrict__ wr, const float* __restrict__ wi,
             float* __restrict__ yr, float* __restrict__ yi,
             int Cin, int Cout)
{
    __shared__ float sxr[18*35];
    __shared__ float sxi[CPLX ? 18*35 : 1];
    __shared__ u64 swr2[COUT_T*9];   // {wr,wr} duplicated
    __shared__ u64 swi2[COUT_T*9];   // {wi,wi} duplicated

    const int t  = threadIdx.x;
    const int tx = t & 15;
    const int ty = t >> 4;
    const int wbase = blockIdx.x * 32;
    const int hbase = blockIdx.y * 16;
    const int groups = Cout / COUT_T;
    const int cog = blockIdx.z % groups;
    const int n   = blockIdx.z / groups;
    const int cobase = cog * COUT_T;

    u64 accRp[COUT_T];
    u64 accRm[CPLX ? COUT_T : 1];
    u64 accI [COUT_T];
#pragma unroll
    for (int co = 0; co < COUT_T; ++co) {
        accRp[co] = 0ull; accI[co] = 0ull;
        if (CPLX) accRm[co] = 0ull;
    }

    for (int ci = 0; ci < Cin; ++ci) {
        const float* pr = xr + ((size_t)(n*Cin + ci))*HW;
        const float* pi = CPLX ? (xi + ((size_t)(n*Cin + ci))*HW) : nullptr;

        for (int idx = t; idx < 18*34; idx += 256) {
            int r = idx / 34, c = idx - r*34;
            int gh = hbase - 1 + r, gw = wbase - 1 + c;
            bool ok = ((unsigned)gh < HH) && ((unsigned)gw < WW);
            sxr[r*35 + c] = ok ? pr[gh*WW + gw] : 0.f;
            if (CPLX) sxi[r*35 + c] = ok ? pi[gh*WW + gw] : 0.f;
        }
        if (t < COUT_T*9) {
            int co = t / 9, k = t - co*9;
            float a = wr[((size_t)(cobase+co)*Cin + ci)*9 + k];
            float b = wi[((size_t)(cobase+co)*Cin + ci)*9 + k];
            swr2[t] = pk2(a, a);
            swi2[t] = pk2(b, b);
        }
        __syncthreads();

        // pack 3x3 windows for the 2-pixel pair
        u64 a2r[9], a2i[CPLX ? 9 : 1];
#pragma unroll
        for (int r = 0; r < 3; ++r) {
            float v0 = sxr[(ty+r)*35 + 2*tx + 0];
            float v1 = sxr[(ty+r)*35 + 2*tx + 1];
            float v2 = sxr[(ty+r)*35 + 2*tx + 2];
            float v3 = sxr[(ty+r)*35 + 2*tx + 3];
            a2r[r*3+0] = pk2(v0, v1);
            a2r[r*3+1] = pk2(v1, v2);
            a2r[r*3+2] = pk2(v2, v3);
            if (CPLX) {
                float u0 = sxi[(ty+r)*35 + 2*tx + 0];
                float u1 = sxi[(ty+r)*35 + 2*tx + 1];
                float u2 = sxi[(ty+r)*35 + 2*tx + 2];
                float u3 = sxi[(ty+r)*35 + 2*tx + 3];
                a2i[r*3+0] = pk2(u0, u1);
                a2i[r*3+1] = pk2(u1, u2);
                a2i[r*3+2] = pk2(u2, u3);
            }
        }

#pragma unroll
        for (int co = 0; co < COUT_T; ++co) {
#pragma unroll
            for (int k = 0; k < 9; ++k) {
                u64 w_r = swr2[co*9 + k];
                u64 w_i = swi2[co*9 + k];
                fma2(accRp[co], a2r[k], w_r);   // + ar*wr
                fma2(accI [co], a2r[k], w_i);   // + ar*wi
                if (CPLX) {
                    fma2(accRm[co], a2i[k], w_i); // (to subtract) ai*wi
                    fma2(accI [co], a2i[k], w_r); // + ai*wr
                }
            }
        }
        __syncthreads();
    }

    const int h = hbase + ty, w0 = wbase + 2*tx;
#pragma unroll
    for (int co = 0; co < COUT_T; ++co) {
        size_t o = ((size_t)(n*Cout + cobase + co))*HW + h*WW + w0;
        float rp0, rp1, i0, i1;
        upk2(accRp[co], rp0, rp1);
        upk2(accI[co],  i0,  i1);
        if (CPLX) {
            float rm0, rm1; upk2(accRm[co], rm0, rm1);
            rp0 -= rm0; rp1 -= rm1;
        }
        *reinterpret_cast<float2*>(yr + o) = make_float2(rp0, rp1);
        *reinterpret_cast<float2*>(yi + o) = make_float2(i0, i1);
    }
}

// ---------------- BN stats, stage 1: partial sums per (c, n, chunk) --------
#define SPLIT 4
#define CHUNK (HW/SPLIT)   // 7168
__global__ void bn_stats1(const float* __restrict__ x, int C,
                          float2* __restrict__ part)
{
    const int c = blockIdx.x, y = blockIdx.y;         // y in [0, NN*SPLIT)
    const int n = y >> 2, chunk = y & 3;
    const int t = threadIdx.x;
    const float4* p = reinterpret_cast<const float4*>(
        x + ((size_t)(n*C + c))*HW + (size_t)chunk*CHUNK);
    float s = 0.f, q = 0.f;
    for (int i = t; i < CHUNK/4; i += 256) {          // 7 iters
        float4 v = p[i];
        s += v.x + v.y + v.z + v.w;
        q = fmaf(v.x, v.x, q); q = fmaf(v.y, v.y, q);
        q = fmaf(v.z, v.z, q); q = fmaf(v.w, v.w, q);
    }
    __shared__ float ss[256], sq[256];
    ss[t] = s; sq[t] = q;
    __syncthreads();
    for (int o = 128; o > 0; o >>= 1) {
        if (t < o) { ss[t] += ss[t+o]; sq[t] += sq[t+o]; }
        __syncthreads();
    }
    if (t == 0) part[c*(NN*SPLIT) + y] = make_float2(ss[0], sq[0]);
}

// ---------------- BN stats, stage 2: 16 partials -> mean/rstd ---------------
__global__ void bn_stats2(const float2* __restrict__ part,
                          float* __restrict__ mean, float* __restrict__ rstd)
{
    const int c = blockIdx.x;
    if (threadIdx.x == 0) {
        double s = 0.0, q = 0.0;
        for (int i = 0; i < NN*SPLIT; ++i) {
            float2 v = part[c*(NN*SPLIT) + i];
            s += (double)v.x; q += (double)v.y;
        }
        double cnt = (double)NN * HW;
        double m = s / cnt;
        double var = q / cnt - m*m;
        mean[c] = (float)m;
        rstd[c] = (float)(1.0 / sqrt(var + 1e-5));
    }
}

// ---------------- BN apply + ReLU (in place, float4) -----------------------
__global__ void bn_apply_relu4(float* __restrict__ x, int C,
                               const float* __restrict__ mean,
                               const float* __restrict__ rstd,
                               const float* __restrict__ g,
                               const float* __restrict__ b)
{
    const int c = blockIdx.y, n = blockIdx.z;
    const float sc = rstd[c] * g[c];
    const float bi = b[c] - mean[c] * sc;
    float4* p = reinterpret_cast<float4*>(x + ((size_t)(n*C + c))*HW);
    int i = blockIdx.x*256 + threadIdx.x;   // HW/4 = 7168 elements of float4
    float4 v = p[i];
    v.x = fmaxf(fmaf(v.x, sc, bi), 0.f);
    v.y = fmaxf(fmaf(v.y, sc, bi), 0.f);
    v.z = fmaxf(fmaf(v.z, sc, bi), 0.f);
    v.w = fmaxf(fmaf(v.w, sc, bi), 0.f);
    p[i] = v;
}

// ------- layer-4 fused: BN(r), BN(i), ReLU, |z|  -> m ------------------------
__global__ void bn_relu_mag4(const float* __restrict__ xr,
                             const float* __restrict__ xi,
                             float* __restrict__ m, int C,
                             const float* __restrict__ mr, const float* __restrict__ sr,
                             const float* __restrict__ mi, const float* __restrict__ si,
                             const float* __restrict__ g,  const float* __restrict__ b)
{
    const int c = blockIdx.y, n = blockIdx.z;
    const float scr = sr[c] * g[c];
    const float bir = b[c] - mr[c] * scr;
    const float sci = si[c] * g[c];
    const float bii = b[c] - mi[c] * sci;
    size_t base = ((size_t)(n*C + c))*HW;
    const float4* pr = reinterpret_cast<const float4*>(xr + base);
    const float4* pi = reinterpret_cast<const float4*>(xi + base);
    float4* pm = reinterpret_cast<float4*>(m + base);
    int i = blockIdx.x*256 + threadIdx.x;
    float4 vr = pr[i], vi = pi[i], vo;
    float a, bb;
    a = fmaxf(fmaf(vr.x, scr, bir), 0.f); bb = fmaxf(fmaf(vi.x, sci, bii), 0.f);
    vo.x = sqrtf(a*a + bb*bb);
    a = fmaxf(fmaf(vr.y, scr, bir), 0.f); bb = fmaxf(fmaf(vi.y, sci, bii), 0.f);
    vo.y = sqrtf(a*a + bb*bb);
    a = fmaxf(fmaf(vr.z, scr, bir), 0.f); bb = fmaxf(fmaf(vi.z, sci, bii), 0.f);
    vo.z = sqrtf(a*a + bb*bb);
    a = fmaxf(fmaf(vr.w, scr, bir), 0.f); bb = fmaxf(fmaf(vi.w, sci, bii), 0.f);
    vo.w = sqrtf(a*a + bb*bb);
    pm[i] = vo;
}

// ---------------- head: 96 -> 3 channels (f32x2 packed) --------------------
__global__ __launch_bounds__(256)
void conv_head(const float* __restrict__ m,
               const float* __restrict__ wc, const float* __restrict__ bc,
               const float* __restrict__ wg, const float* __restrict__ bg,
               float* __restrict__ out)
{
    __shared__ float sm[18*35];
    __shared__ u64 sw2[3*9];
    const int t = threadIdx.x;
    const int tx = t & 15, ty = t >> 4;
    const int wbase = blockIdx.x * 32, hbase = blockIdx.y * 16;
    const int n = blockIdx.z;

    u64 acc[3] = {0ull, 0ull, 0ull};
    for (int ci = 0; ci < 96; ++ci) {
        const float* p = m + ((size_t)(n*96 + ci))*HW;
        for (int idx = t; idx < 18*34; idx += 256) {
            int r = idx / 34, c = idx - r*34;
            int gh = hbase - 1 + r, gw = wbase - 1 + c;
            sm[r*35 + c] = (((unsigned)gh < HH) && ((unsigned)gw < WW))
                           ? p[gh*WW + gw] : 0.f;
        }
        if (t < 27) {
            int co = t / 9, k = t - co*9;
            float w = (co == 0) ? wc[(size_t)ci*9 + k]
                                : wg[((size_t)(co-1)*96 + ci)*9 + k];
            sw2[t] = pk2(w, w);
        }
        __syncthreads();
        u64 a2[9];
#pragma unroll
        for (int r = 0; r < 3; ++r) {
            float v0 = sm[(ty+r)*35 + 2*tx + 0];
            float v1 = sm[(ty+r)*35 + 2*tx + 1];
            float v2 = sm[(ty+r)*35 + 2*tx + 2];
            float v3 = sm[(ty+r)*35 + 2*tx + 3];
            a2[r*3+0] = pk2(v0, v1);
            a2[r*3+1] = pk2(v1, v2);
            a2[r*3+2] = pk2(v2, v3);
        }
#pragma unroll
        for (int co = 0; co < 3; ++co)
#pragma unroll
            for (int k = 0; k < 9; ++k)
                fma2(acc[co], a2[k], sw2[co*9 + k]);
        __syncthreads();
    }
    const int h = hbase + ty, w0 = wbase + 2*tx;
    const float b0 = bc[0], b1 = bg[0], b2 = bg[1];
    float c0a, c0b, c1a, c1b, c2a, c2b;
    upk2(acc[0], c0a, c0b);
    upk2(acc[1], c1a, c1b);
    upk2(acc[2], c2a, c2b);
    c0a += b0; c0b += b0;
    c0a = 1.f / (1.f + expf(-c0a));
    c0b = 1.f / (1.f + expf(-c0b));
    size_t o0 = ((size_t)(n*3 + 0))*HW + h*WW + w0;
    size_t o1 = ((size_t)(n*3 + 1))*HW + h*WW + w0;
    size_t o2 = ((size_t)(n*3 + 2))*HW + h*WW + w0;
    *reinterpret_cast<float2*>(out + o0) = make_float2(c0a, c0b);
    *reinterpret_cast<float2*>(out + o1) = make_float2(c1a + b1, c1b + b1);
    *reinterpret_cast<float2*>(out + o2) = make_float2(c2a + b2, c2b + b2);
}

// ---------------- driver -----------------------------------------------------
extern "C" void kernel_launch(void* const* d_in, const int* in_sizes, int n_in,
                              void* d_out, int out_size)
{
    (void)in_sizes; (void)n_in; (void)out_size;
    const float* x   = (const float*)d_in[0];
    const float* w1r = (const float*)d_in[1];
    const float* w1i = (const float*)d_in[2];
    const float* g1  = (const float*)d_in[3];
    const float* b1  = (const float*)d_in[4];
    const float* w2r = (const float*)d_in[5];
    const float* w2i = (const float*)d_in[6];
    const float* g2  = (const float*)d_in[7];
    const float* b2  = (const float*)d_in[8];
    const float* w3r = (const float*)d_in[9];
    const float* w3i = (const float*)d_in[10];
    const float* g3  = (const float*)d_in[11];
    const float* b3  = (const float*)d_in[12];
    const float* w4r = (const float*)d_in[13];
    const float* w4i = (const float*)d_in[14];
    const float* g4  = (const float*)d_in[15];
    const float* b4  = (const float*)d_in[16];
    const float* wc  = (const float*)d_in[17];
    const float* bc  = (const float*)d_in[18];
    const float* wg  = (const float*)d_in[19];
    const float* bg  = (const float*)d_in[20];
    float* out = (float*)d_out;

    float *Ar, *Ai, *Br, *Bi, *mr, *sr, *mi, *si;
    float2 *pR, *pI;
    cudaGetSymbolAddress((void**)&Ar, g_Ar);
    cudaGetSymbolAddress((void**)&Ai, g_Ai);
    cudaGetSymbolAddress((void**)&Br, g_Br);
    cudaGetSymbolAddress((void**)&Bi, g_Bi);
    cudaGetSymbolAddress((void**)&mr, g_mr);
    cudaGetSymbolAddress((void**)&sr, g_sr);
    cudaGetSymbolAddress((void**)&mi, g_mi);
    cudaGetSymbolAddress((void**)&si, g_si);
    cudaGetSymbolAddress((void**)&pR, g_partR);
    cudaGetSymbolAddress((void**)&pI, g_partI);

    const dim3 blk(256);
    const dim3 ew(HW/(4*256), 144, NN);   // per-C elementwise grid (set .y per layer)

    // Layer 1: real input -> complex (256 -> 144)
    conv3x3<8, false><<<dim3(7, 8, NN*(144/8)), blk>>>(x, nullptr, w1r, w1i,
                                                       Ar, Ai, 256, 144);
    bn_stats1<<<dim3(144, NN*SPLIT), blk>>>(Ar, 144, pR);
    bn_stats1<<<dim3(144, NN*SPLIT), blk>>>(Ai, 144, pI);
    bn_stats2<<<144, 32>>>(pR, mr, sr);
    bn_stats2<<<144, 32>>>(pI, mi, si);
    bn_apply_relu4<<<dim3(28, 144, NN), blk>>>(Ar, 144, mr, sr, g1, b1);
    bn_apply_relu4<<<dim3(28, 144, NN), blk>>>(Ai, 144, mi, si, g1, b1);

    // Layer 2: complex (144 -> 96)
    conv3x3<8, true><<<dim3(7, 8, NN*(96/8)), blk>>>(Ar, Ai, w2r, w2i,
                                                     Br, Bi, 144, 96);
    bn_stats1<<<dim3(96, NN*SPLIT), blk>>>(Br, 96, pR);
    bn_stats1<<<dim3(96, NN*SPLIT), blk>>>(Bi, 96, pI);
    bn_stats2<<<96, 32>>>(pR, mr, sr);
    bn_stats2<<<96, 32>>>(pI, mi, si);
    bn_apply_relu4<<<dim3(28, 96, NN), blk>>>(Br, 96, mr, sr, g2, b2);
    bn_apply_relu4<<<dim3(28, 96, NN), blk>>>(Bi, 96, mi, si, g2, b2);

    // Layer 3: complex (96 -> 96)
    conv3x3<8, true><<<dim3(7, 8, NN*(96/8)), blk>>>(Br, Bi, w3r, w3i,
                                                     Ar, Ai, 96, 96);
    bn_stats1<<<dim3(96, NN*SPLIT), blk>>>(Ar, 96, pR);
    bn_stats1<<<dim3(96, NN*SPLIT), blk>>>(Ai, 96, pI);
    bn_stats2<<<96, 32>>>(pR, mr, sr);
    bn_stats2<<<96, 32>>>(pI, mi, si);
    bn_apply_relu4<<<dim3(28, 96, NN), blk>>>(Ar, 96, mr, sr, g3, b3);
    bn_apply_relu4<<<dim3(28, 96, NN), blk>>>(Ai, 96, mi, si, g3, b3);

    // Layer 4: complex (96 -> 96), fused BN+ReLU+|z| into Ar
    conv3x3<8, true><<<dim3(7, 8, NN*(96/8)), blk>>>(Ar, Ai, w4r, w4i,
                                                     Br, Bi, 96, 96);
    bn_stats1<<<dim3(96, NN*SPLIT), blk>>>(Br, 96, pR);
    bn_stats1<<<dim3(96, NN*SPLIT), blk>>>(Bi, 96, pI);
    bn_stats2<<<96, 32>>>(pR, mr, sr);
    bn_stats2<<<96, 32>>>(pI, mi, si);
    bn_relu_mag4<<<dim3(28, 96, NN), blk>>>(Br, Bi, Ar, 96,
                                            mr, sr, mi, si, g4, b4);

    // head (ch0 sigmoid)
    conv_head<<<dim3(7, 8, NN), blk>>>(Ar, wc, bc, wg, bg, out);
}